// round 1
// baseline (speedup 1.0000x reference)
#include <cuda_runtime.h>
#include <cuda_bf16.h>

// Layout / config
#define WARPS_PER_BLOCK 8
#define NIMG 2                       // images per warp
#define IMGS_PER_BLOCK (WARPS_PER_BLOCK * NIMG)   // 16
#define B_TOTAL 8192
#define GRID (B_TOTAL / IMGS_PER_BLOCK)           // 512
#define W2_STRIDE 11                  // 10 outputs padded to 11 (bank-conflict-free)
#define W2_FLOATS (784 * W2_STRIDE)   // 8624
#define MEAS_FLOATS (WARPS_PER_BLOCK * NIMG * 784)
#define SMEM_BYTES ((W2_FLOATS + MEAS_FLOATS) * sizeof(float))

// Scratch (no allocation allowed)
__device__ float g_W2[W2_FLOATS];   // [i=4p+j][o] padded stride 11
__device__ float g_b2[10];
__device__ float g_trig[16];        // cv0[0..3] sv0[4..7] cw[8..11] sw[12..15]

// ---------------------------------------------------------------------------
// Setup: fold map_w into lin_w (W2), fold map_b/lin_b into b2, precompute trig
// ---------------------------------------------------------------------------
__global__ void setup_kernel(const float* __restrict__ var_params,
                             const float* __restrict__ map_w,
                             const float* __restrict__ map_b,
                             const float* __restrict__ lin_w,
                             const float* __restrict__ lin_b) {
    int blk = blockIdx.x;
    int tid = threadIdx.x;
    if (blk < 31) {
        int idx = blk * 256 + tid;          // 0..7839 -> (i, o)
        if (idx < 7840) {
            int i = idx / 10;
            int o = idx - i * 10;
            int p = i >> 2;
            int j = i & 3;
            const float* lw = lin_w + o * 1568 + 8 * p;
            float acc = 0.0f;
#pragma unroll
            for (int k = 0; k < 8; k++)
                acc += lw[k] * map_w[k * 4 + j];
            g_W2[i * W2_STRIDE + o] = acc;
        }
    } else if (blk == 31) {
        // b2[o] = lin_b[o] + sum_t lin_w[o, t] * map_b[t % 8]
        int w = tid >> 5, lane = tid & 31;
        for (int o = w; o < 10; o += 8) {
            float acc = 0.0f;
            for (int t = lane; t < 1568; t += 32)
                acc += lin_w[o * 1568 + t] * map_b[t & 7];
#pragma unroll
            for (int s = 16; s; s >>= 1)
                acc += __shfl_xor_sync(0xFFFFFFFFu, acc, s);
            if (lane == 0) g_b2[o] = acc + lin_b[o];
        }
    } else {
        if (tid < 4) {
            float v0 = var_params[tid];
            float v1 = var_params[4 + tid];
            g_trig[tid]      = cosf(v0);
            g_trig[4 + tid]  = sinf(v0);
            g_trig[8 + tid]  = cosf(v1);
            g_trig[12 + tid] = sinf(v1);
        }
    }
}

// ---------------------------------------------------------------------------
// Fused main kernel
// ---------------------------------------------------------------------------
__global__ __launch_bounds__(256, 2)
void quanv_kernel(const float* __restrict__ x, float* __restrict__ out) {
    extern __shared__ float smem[];
    float* W2s   = smem;                 // [784][11]
    float* measb = smem + W2_FLOATS;     // [WARPS][NIMG][784]

    int tid = threadIdx.x;

    // Stage W2 into shared
    for (int idx = tid; idx < W2_FLOATS; idx += 256)
        W2s[idx] = g_W2[idx];

    // Trig constants to registers
    float cv0[4], sv0[4], cwv[4], swv[4];
#pragma unroll
    for (int j = 0; j < 4; j++) {
        cv0[j] = g_trig[j];
        sv0[j] = g_trig[4 + j];
        cwv[j] = g_trig[8 + j];
        swv[j] = g_trig[12 + j];
    }
    __syncthreads();

    int w    = tid >> 5;
    int lane = tid & 31;
    int img_base = blockIdx.x * IMGS_PER_BLOCK + w * NIMG;
    float* mymeas = measb + (size_t)w * NIMG * 784;

    // -------- Phase 1: patch circuit -> meas[m][784] --------
#pragma unroll
    for (int m = 0; m < NIMG; m++) {
        const float* img = x + (size_t)(img_base + m) * 784;
        for (int p = lane; p < 196; p += 32) {
            int pr = p / 14;
            int pc = p - pr * 14;
            const float* base = img + pr * 56 + pc * 2;
            float2 r0 = *reinterpret_cast<const float2*>(base);
            float2 r1 = *reinterpret_cast<const float2*>(base + 28);
            float a0 = r0.x, a1 = r0.y, a2 = r1.x, a3 = r1.y;
            float C[4], S[4];
            float av[4] = {a0, a1, a2, a3};
#pragma unroll
            for (int j = 0; j < 4; j++) {
                float t  = av[j] * (1.0f / 255.0f);     // < 0.004
                float t2 = t * t;
                float sa = t * (1.0f - t2 * (1.0f / 6.0f));  // sin(t), exact to ulp
                float ca = 1.0f - 0.5f * t2;                 // cos(t), exact to ulp
                C[j] = cv0[j] * ca - sv0[j] * sa;            // cos(t + v0)
                S[j] = sv0[j] * ca + cv0[j] * sa;            // sin(t + v0)
            }
            float P0 = C[0];
            float P1 = P0 * C[1];
            float P2 = P1 * C[2];
            float P3 = P2 * C[3];
            float4 z;
            z.x = cwv[0] * P0 - swv[0] * (S[0] * S[1]);
            z.y = cwv[1] * P1 - swv[1] * (S[1] * S[2]);
            z.z = cwv[2] * P2 - swv[2] * (S[2] * S[3]);
            z.w = cwv[3] * P3 - swv[3] * S[3];
            *reinterpret_cast<float4*>(&mymeas[m * 784 + 4 * p]) = z;
        }
    }
    __syncwarp();

    // -------- Phase 2: logits[o] = sum_i meas[m][i] * W2[i][o] --------
    float acc[NIMG][10];
#pragma unroll
    for (int m = 0; m < NIMG; m++)
#pragma unroll
        for (int o = 0; o < 10; o++)
            acc[m][o] = 0.0f;

    for (int i = lane; i < 784; i += 32) {
        float m0 = mymeas[i];
        float m1 = mymeas[784 + i];
        const float* wrow = &W2s[i * W2_STRIDE];
#pragma unroll
        for (int o = 0; o < 10; o++) {
            float ww = wrow[o];
            acc[0][o] += m0 * ww;
            acc[1][o] += m1 * ww;
        }
    }

    // warp butterfly reduce (all lanes end with totals)
#pragma unroll
    for (int m = 0; m < NIMG; m++)
#pragma unroll
        for (int o = 0; o < 10; o++)
#pragma unroll
            for (int s = 16; s; s >>= 1)
                acc[m][o] += __shfl_xor_sync(0xFFFFFFFFu, acc[m][o], s);

    // -------- Phase 3: bias + log_softmax, lane m handles image m --------
    if (lane < NIMG) {
        int m = lane;
        float l[10];
        float mx = -1e30f;
#pragma unroll
        for (int o = 0; o < 10; o++) {
            l[o] = acc[m][o] + g_b2[o];
            mx = fmaxf(mx, l[o]);
        }
        float sum = 0.0f;
#pragma unroll
        for (int o = 0; o < 10; o++)
            sum += __expf(l[o] - mx);
        float lse = mx + __logf(sum);
        float* op = out + (size_t)(img_base + m) * 10;
#pragma unroll
        for (int o = 0; o < 10; o++)
            op[o] = l[o] - lse;
    }
}

// ---------------------------------------------------------------------------
extern "C" void kernel_launch(void* const* d_in, const int* in_sizes, int n_in,
                              void* d_out, int out_size) {
    const float* x          = (const float*)d_in[0];
    const float* var_params = (const float*)d_in[1];
    const float* map_w      = (const float*)d_in[2];
    const float* map_b      = (const float*)d_in[3];
    const float* lin_w      = (const float*)d_in[4];
    const float* lin_b      = (const float*)d_in[5];
    float* out = (float*)d_out;

    setup_kernel<<<33, 256>>>(var_params, map_w, map_b, lin_w, lin_b);

    cudaFuncSetAttribute(quanv_kernel,
                         cudaFuncAttributeMaxDynamicSharedMemorySize,
                         (int)SMEM_BYTES);
    quanv_kernel<<<GRID, 256, SMEM_BYTES>>>(x, out);
}